// round 11
// baseline (speedup 1.0000x reference)
#include <cuda_runtime.h>
#include <cfloat>
#include <climits>
#include <math.h>

// Beam search step: P=32 prompts, D=8 beams, V=128000, S=2048.
// Ordering by alive_lp + log(p) == ordering by m = p * exp(alive_lp) (monotone).
// k0: sampled bound per half-beam: min of 16 disjoint 500-elem chunk maxima,
//     scaled; atomicMax over all half-beams -> tau <= global scaled 16th and
//     tight (tracks the dominant beam). tau0 likewise for beam-0 raw.
// k1: SINGLE streaming pass; append elements with v*scale >= tau.
// k2: exact top-16 via register tournament + beam-search selection; resets state.
// k3: 512-block gather/convert of output sequence rows.

#define P_ 32
#define D_ 8
#define V_ 128000
#define S_ 2048
#define NBLK 32          // blocks per prompt in k1 (4 per beam)
#define CHUNK 32000      // elements per k1 block (V/4)
#define EOS_ID 2
#define MASK_INF 10000000.0f
#define PADV (-FLT_MAX)
#define CAP  32768       // candidate capacity per prompt (scaled list)
#define CAP0 8192        // candidate capacity per prompt (beam-0 raw list)
#define TILE 4096        // candidates per tournament tile (16 reg slots * 256 thr)

// output layout (flat float32, tuple concat order)
#define OFF_ATTN 0
#define OFF_ASEQ 256
#define OFF_ALP  524544
#define OFF_FSEQ 524800
#define OFF_FLP  1049088

__device__ int   g_taub[P_];             // tau as positive-float bits (atomicMax)
__device__ int   g_tau0b[P_];
__device__ int   g_cnt[P_];              // zero-init at load; k2 resets
__device__ int   g_cnt0[P_];
__device__ float g_cv[P_ * CAP];
__device__ int   g_ci[P_ * CAP];
__device__ float g_c0v[P_ * CAP0];
__device__ int   g_c0i[P_ * CAP0];
__device__ int4  g_desc[2 * P_ * D_];    // {buf(0=alive,1=fin), src_beam, token, subpos(-1 none)}

#define FULLM 0xffffffffu

__device__ __forceinline__ float max4(float4 v) {
    return fmaxf(fmaxf(v.x, v.y), fmaxf(v.z, v.w));
}

// ---------------- Kernel 0: sampled per-half-beam bounds ---------------------
// 16 blocks/prompt = 2 per beam. Each block: 16 disjoint chunks (500 elems) of
// its 64000-elem half-beam; bound = min(chunk maxima) * scale_d. Positive
// floats are int-ordered, so atomicMax on the bit pattern combines bounds.
__global__ void __launch_bounds__(256)
k0_tau(const float* __restrict__ probs, const float* __restrict__ alive_lp,
       const int* __restrict__ still_prompt) {
    int blk = blockIdx.x;
    int p = blk >> 4;
    if (still_prompt[p]) return;
    int s = blk & 15;
    int d = s >> 1;
    int h = s & 1;
    int t = threadIdx.x, w = t >> 5, lane = t & 31;

    __shared__ float scm[16];

    const float4* base = (const float4*)(probs + (long)(p * D_ + d) * V_ + h * 64000);
    // chunk c: float4 range [c*1000, c*1000+125)
#pragma unroll
    for (int cc = 0; cc < 2; cc++) {
        int c = w + cc * 8;
        const float4* cb = base + c * 1000;
        float m = -FLT_MAX;
        for (int i = lane; i < 125; i += 32) m = fmaxf(m, max4(cb[i]));
#pragma unroll
        for (int off = 16; off; off >>= 1) m = fmaxf(m, __shfl_xor_sync(FULLM, m, off));
        if (lane == 0) scm[c] = m;
    }
    __syncthreads();
    if (t == 0) {
        float mn = scm[0];
#pragma unroll
        for (int i = 1; i < 16; i++) mn = fminf(mn, scm[i]);
        float scale = expf(alive_lp[p * D_ + d]);
        atomicMax(&g_taub[p], __float_as_int(mn * scale));
        if (d == 0) atomicMax(&g_tau0b[p], __float_as_int(mn));
    }
}

// ---------------- Kernel 1: single-pass streaming filter ---------------------
__global__ void __launch_bounds__(256)
k1_scan(const float* __restrict__ probs, const float* __restrict__ alive_lp,
        const int* __restrict__ still_prompt, const int* __restrict__ is_first) {
    int blk = blockIdx.x;
    int p = blk >> 5;
    if (still_prompt[p]) return;              // passthrough prompt: no work
    int b = blk & 31;
    int d = b >> 2;
    int quar = b & 3;
    int t = threadIdx.x;

    float tau  = __int_as_float(g_taub[p]);
    float tau0 = __int_as_float(g_tau0b[p]);
    float scale = expf(alive_lp[p * D_ + d]);
    bool do0 = (d == 0) && (is_first[p] != 0);
    const float4* base = (const float4*)(probs + (long)(p * D_ + d) * V_ + quar * CHUNK);
    int fb0 = d * V_ + quar * CHUNK;
    const int N4 = CHUNK / 4;                 // 8000 float4s
    const float4 pad4 = make_float4(PADV, PADV, PADV, PADV);

    for (int j0 = t; j0 < N4; j0 += 1024) {
        int j1 = j0 + 256, j2 = j0 + 512, j3 = j0 + 768;
        float4 va = __ldcs(base + j0);
        float4 vb = (j1 < N4) ? __ldcs(base + j1) : pad4;
        float4 vc = (j2 < N4) ? __ldcs(base + j2) : pad4;
        float4 vd = (j3 < N4) ? __ldcs(base + j3) : pad4;

        float vmax = fmaxf(fmaxf(max4(va), max4(vb)), fmaxf(max4(vc), max4(vd)));
        bool trig = (vmax * scale >= tau) || (do0 && vmax >= tau0);

        if (__ballot_sync(FULLM, trig)) {     // rare with tight tau
            float4 q[4] = {va, vb, vc, vd};
            int js[4] = {j0, j1, j2, j3};
#pragma unroll
            for (int u = 0; u < 4; u++) {
                if (js[u] >= N4) continue;
                int fb = fb0 + js[u] * 4;
                float vx[4] = {q[u].x, q[u].y, q[u].z, q[u].w};
#pragma unroll
                for (int c = 0; c < 4; c++) {
                    float sval = vx[c] * scale;
                    if (sval >= tau) {
                        int pos = atomicAdd(&g_cnt[p], 1);
                        if (pos < CAP) { g_cv[p * CAP + pos] = sval; g_ci[p * CAP + pos] = fb + c; }
                    }
                    if (do0 && vx[c] >= tau0) {       // d==0: flat idx == token id
                        int pos0 = atomicAdd(&g_cnt0[p], 1);
                        if (pos0 < CAP0) { g_c0v[p * CAP0 + pos0] = vx[c]; g_c0i[p * CAP0 + pos0] = fb + c; }
                    }
                }
            }
        }
    }
}

// ---------------- block tournament: exact sorted top-16 of (gv,gi)[0..cnt) ---
// 256 threads. Result in bestv/besti (smem[16]), DESC value, ASC idx tie-break.
struct TournScratch {
    float swv[8]; int swi[8]; int swt[8];
    int   s_win;
};

__device__ void block_top16(const float* __restrict__ gv, const int* __restrict__ gi,
                            int cnt, volatile float* bestv, volatile int* besti,
                            TournScratch* sc) {
    int t = threadIdx.x, w = t >> 5, lane = t & 31;
    float rv[17]; int ri[17];
    int ntile = (cnt + TILE - 1) / TILE;
    if (ntile < 1) ntile = 1;

    for (int tile = 0; tile < ntile; tile++) {
        int base = tile * TILE;
#pragma unroll
        for (int k = 0; k < 16; k++) {
            int j = base + k * 256 + t;
            bool ok = (j < cnt);
            rv[k] = ok ? gv[j] : -FLT_MAX;
            ri[k] = ok ? gi[j] : INT_MAX;
        }
        if (tile > 0 && t < 16) { rv[16] = bestv[t]; ri[16] = besti[t]; }
        else                    { rv[16] = -FLT_MAX; ri[16] = INT_MAX; }
        __syncthreads();

        for (int r = 0; r < 16; r++) {
            float bv = rv[0]; int bi = ri[0]; int bs = 0;
#pragma unroll
            for (int k = 1; k < 17; k++)
                if (rv[k] > bv || (rv[k] == bv && ri[k] < bi)) { bv = rv[k]; bi = ri[k]; bs = k; }
            int bt = t;
#pragma unroll
            for (int off = 16; off; off >>= 1) {
                float ov = __shfl_xor_sync(FULLM, bv, off);
                int   oi = __shfl_xor_sync(FULLM, bi, off);
                int   ot = __shfl_xor_sync(FULLM, bt, off);
                if (ov > bv || (ov == bv && oi < bi)) { bv = ov; bi = oi; bt = ot; }
            }
            if (lane == 0) { sc->swv[w] = bv; sc->swi[w] = bi; sc->swt[w] = bt; }
            __syncthreads();
            if (t == 0) {
                float fv = sc->swv[0]; int fi = sc->swi[0]; int ft = sc->swt[0];
#pragma unroll
                for (int q = 1; q < 8; q++)
                    if (sc->swv[q] > fv || (sc->swv[q] == fv && sc->swi[q] < fi)) {
                        fv = sc->swv[q]; fi = sc->swi[q]; ft = sc->swt[q];
                    }
                bestv[r] = fv; besti[r] = fi; sc->s_win = ft;
            }
            __syncthreads();
            if (t == sc->s_win) { rv[bs] = -FLT_MAX; ri[bs] = INT_MAX; }
        }
        __syncthreads();
    }
}

// ---------------- Kernel 2: top-16 + beam-search selection -------------------
__global__ void __launch_bounds__(256)
k2_select(const float* __restrict__ alive_lp, const float* __restrict__ fin_lp,
          const int* __restrict__ still_prompt,
          const int* __restrict__ is_first,
          const int* __restrict__ cur_pos_p, float* __restrict__ out) {
    int p = blockIdx.x;
    int t = threadIdx.x;

    __shared__ float fv[16];  __shared__ int fi[16];
    __shared__ float fv0[16]; __shared__ int fi0[16];
    __shared__ TournScratch sc;

    bool sp = still_prompt[p] != 0;
    bool first = is_first[p] != 0;
    int cnt  = min(g_cnt[p], CAP);
    int cnt0 = min(g_cnt0[p], CAP0);

    if (!sp) {
        block_top16(g_cv + p * CAP, g_ci + p * CAP, cnt, fv, fi, &sc);
        if (first)
            block_top16(g_c0v + p * CAP0, g_c0i + p * CAP0, cnt0, fv0, fi0, &sc);
    }
    __syncthreads();

    if (t == 0) {
        g_cnt[p] = 0; g_cnt0[p] = 0;          // reset for next graph replay
        g_taub[p] = 0; g_tau0b[p] = 0;
        int cp = *cur_pos_p;

        float lp16[16]; int tok16[16], beam16[16]; bool fin16[16];
        if (!sp) {
            for (int k = 0; k < 16; k++) {
                int idx = fi[k];
                int bm = idx / V_;
                beam16[k] = bm;
                tok16[k]  = idx - bm * V_;
                lp16[k]   = logf(fv[k]);      // log(p*e^a) == a + log p
            }
            if (first) {
                float al0 = alive_lp[p * D_];
                for (int k = 0; k < 16; k++) {
                    tok16[k] = fi0[k];        // flat idx within beam 0 == token
                    lp16[k]  = al0 + logf(fv0[k]);
                }
            }
            for (int k = 0; k < 16; k++) fin16[k] = (tok16[k] == EOS_ID);
        }

        int na[8]; float nav[8];
        int nf[8]; float nfv[8];
        if (!sp) {
            float am[16]; bool used[16];
            for (int k = 0; k < 16; k++) { am[k] = lp16[k] + (fin16[k] ? -MASK_INF : 0.0f); used[k] = false; }
            for (int j = 0; j < 8; j++) {
                int bi = -1; float bv = 0.0f;
                for (int k = 0; k < 16; k++)
                    if (!used[k] && (bi < 0 || am[k] > bv)) { bi = k; bv = am[k]; }
                used[bi] = true; na[j] = bi; nav[j] = bv;
            }
            float cl[24]; bool used2[24];
            for (int j = 0; j < 8; j++) cl[j] = fin_lp[p * D_ + j];
            for (int k = 0; k < 16; k++) cl[8 + k] = lp16[k] + (fin16[k] ? 0.0f : -MASK_INF);
            for (int k = 0; k < 24; k++) used2[k] = false;
            for (int j = 0; j < 8; j++) {
                int bi = -1; float bv = 0.0f;
                for (int k = 0; k < 24; k++)
                    if (!used2[k] && (bi < 0 || cl[k] > bv)) { bi = k; bv = cl[k]; }
                used2[bi] = true; nf[j] = bi; nfv[j] = bv;
            }
        }

        for (int j = 0; j < 8; j++) {
            out[OFF_ATTN + p * D_ + j] = sp ? (float)j : (float)beam16[na[j]];
            out[OFF_ALP  + p * D_ + j] = sp ? alive_lp[p * D_ + j] : nav[j];
            out[OFF_FLP  + p * D_ + j] = sp ? fin_lp[p * D_ + j]   : nfv[j];

            int4 da, df;
            if (sp) {
                da = make_int4(0, j, 0, -1);
                df = make_int4(1, j, 0, -1);
            } else {
                da = make_int4(0, beam16[na[j]], tok16[na[j]], cp);
                if (nf[j] < 8) df = make_int4(1, nf[j], 0, -1);
                else { int k = nf[j] - 8; df = make_int4(0, beam16[k], tok16[k], cp); }
            }
            g_desc[p * D_ + j] = da;
            g_desc[P_ * D_ + p * D_ + j] = df;
        }
    }
}

// ---------------- Kernel 3: gather output sequences --------------------------
__global__ void __launch_bounds__(256)
k3_gather(const int* __restrict__ alive_seq, const int* __restrict__ fin_seq,
          float* __restrict__ out) {
    int r = blockIdx.x;                       // 0..511
    int4 dsc = g_desc[r];
    bool isAlive = r < P_ * D_;
    int rr = isAlive ? r : r - P_ * D_;
    int p = rr >> 3;
    const int* srcbase = (dsc.x ? fin_seq : alive_seq) + (long)(p * D_ + dsc.y) * S_;
    long dst = (isAlive ? (long)OFF_ASEQ : (long)OFF_FSEQ) + (long)rr * S_;
    const int4* s4 = (const int4*)srcbase;
    float4* o4 = (float4*)(out + dst);
    int subpos = dsc.w, tok = dsc.z;
    for (int j = threadIdx.x; j < S_ / 4; j += 256) {
        int4 v = s4[j];
        int base = j * 4;
        if (subpos >= base && subpos < base + 4) {
            int* vp = (int*)&v;
            vp[subpos - base] = tok;
        }
        o4[j] = make_float4((float)v.x, (float)v.y, (float)v.z, (float)v.w);
    }
}

extern "C" void kernel_launch(void* const* d_in, const int* in_sizes, int n_in,
                              void* d_out, int out_size) {
    const float* probs        = (const float*)d_in[0];
    const int*   alive_seq    = (const int*)d_in[1];
    const int*   fin_seq      = (const int*)d_in[2];
    const float* alive_lp     = (const float*)d_in[3];
    const float* fin_lp       = (const float*)d_in[4];
    const int*   still_prompt = (const int*)d_in[5];
    const int*   is_first     = (const int*)d_in[6];
    const int*   cur_pos      = (const int*)d_in[7];
    float* out = (float*)d_out;

    k0_tau<<<P_ * 16, 256>>>(probs, alive_lp, still_prompt);
    k1_scan<<<P_ * NBLK, 256>>>(probs, alive_lp, still_prompt, is_first);
    k2_select<<<P_, 256>>>(alive_lp, fin_lp, still_prompt, is_first, cur_pos, out);
    k3_gather<<<2 * P_ * D_, 256>>>(alive_seq, fin_seq, out);
}

// round 12
// speedup vs baseline: 1.0629x; 1.0629x over previous
#include <cuda_runtime.h>
#include <cfloat>
#include <climits>
#include <math.h>

// Beam search step: P=32 prompts, D=8 beams, V=128000, S=2048.
// Ordering by alive_lp + log(p) == ordering by m = p * exp(alive_lp) (monotone).
// k1: pass 1 SAMPLES 248 of every 1000 elems (32 disjoint sample-chunks) ->
//     tau_b = 16th largest of the 32 sample-chunk maxima <= block 16th <=
//     global 16th (exact-safe). pass 2 filter-appends >= tau_b (sampled part
//     L2-warm). still_prompt prompts skipped entirely.
// k2: exact top-16 via register tournament + beam-search selection; resets cnt.
// k3: 512-block gather/convert of output sequence rows.

#define P_ 32
#define D_ 8
#define V_ 128000
#define S_ 2048
#define NBLK 32          // blocks per prompt in k1 (4 per beam)
#define CHUNK 32000      // elements per k1 block (V/4)
#define NSUB 32          // sub-chunks per block (1000 elems each)
#define SAMP4 62         // sampled float4s per sub-chunk (of 250) in pass 1
#define EOS_ID 2
#define MASK_INF 10000000.0f
#define PADV (-FLT_MAX)
#define CAP  32768       // candidate capacity per prompt (scaled list)
#define CAP0 8192        // candidate capacity per prompt (beam-0 raw list)
#define TILE 4096        // candidates per tournament tile (16 reg slots * 256 thr)

// output layout (flat float32, tuple concat order)
#define OFF_ATTN 0
#define OFF_ASEQ 256
#define OFF_ALP  524544
#define OFF_FSEQ 524800
#define OFF_FLP  1049088

__device__ int   g_cnt[P_];              // zero-init at load; k2 resets
__device__ int   g_cnt0[P_];
__device__ float g_cv[P_ * CAP];
__device__ int   g_ci[P_ * CAP];
__device__ float g_c0v[P_ * CAP0];
__device__ int   g_c0i[P_ * CAP0];
__device__ int4  g_desc[2 * P_ * D_];    // {buf(0=alive,1=fin), src_beam, token, subpos(-1 none)}

#define FULLM 0xffffffffu

__device__ __forceinline__ float max4(float4 v) {
    return fmaxf(fmaxf(v.x, v.y), fmaxf(v.z, v.w));
}

// ---------------- Kernel 1: sampled self-threshold + filter-append ----------
__global__ void __launch_bounds__(256)
k1_scan(const float* __restrict__ probs, const float* __restrict__ alive_lp,
        const int* __restrict__ still_prompt, const int* __restrict__ is_first) {
    int blk = blockIdx.x;
    int p = blk >> 5;
    if (still_prompt[p]) return;              // passthrough prompt: no work
    int b = blk & 31;
    int d = b >> 2;
    int quar = b & 3;
    int t = threadIdx.x, w = t >> 5, lane = t & 31;

    __shared__ float scm[NSUB];
    __shared__ float s_tau;

    const float4* base = (const float4*)(probs + (long)(p * D_ + d) * V_ + quar * CHUNK);
    const int N4 = CHUNK / 4;                 // 8000 float4s
    const int SUB4 = N4 / NSUB;               // 250 float4s per sub-chunk

    // ---- pass 1: maxima of 32 disjoint SAMPLE chunks (first 62 float4s of
    //      each 250-float4 sub-chunk); 4 independent load streams per lane ----
    {
        const float4* sb0 = base + (w +  0) * SUB4;
        const float4* sb1 = base + (w +  8) * SUB4;
        const float4* sb2 = base + (w + 16) * SUB4;
        const float4* sb3 = base + (w + 24) * SUB4;
        float m0 = -FLT_MAX, m1 = -FLT_MAX, m2 = -FLT_MAX, m3 = -FLT_MAX;
        for (int i = lane; i < SAMP4; i += 32) {
            m0 = fmaxf(m0, max4(sb0[i]));
            m1 = fmaxf(m1, max4(sb1[i]));
            m2 = fmaxf(m2, max4(sb2[i]));
            m3 = fmaxf(m3, max4(sb3[i]));
        }
#pragma unroll
        for (int off = 16; off; off >>= 1) {
            m0 = fmaxf(m0, __shfl_xor_sync(FULLM, m0, off));
            m1 = fmaxf(m1, __shfl_xor_sync(FULLM, m1, off));
            m2 = fmaxf(m2, __shfl_xor_sync(FULLM, m2, off));
            m3 = fmaxf(m3, __shfl_xor_sync(FULLM, m3, off));
        }
        if (lane == 0) { scm[w] = m0; scm[w + 8] = m1; scm[w + 16] = m2; scm[w + 24] = m3; }
    }
    __syncthreads();

    // ---- tau_b = 16th largest of the 32 maxima (warp 0, argmax-invalidate) ----
    if (w == 0) {
        float v = scm[lane];
        float last = -FLT_MAX;
#pragma unroll
        for (int k = 0; k < 16; k++) {
            float bv = v; int bl = lane;
#pragma unroll
            for (int off = 16; off; off >>= 1) {
                float ov = __shfl_xor_sync(FULLM, bv, off);
                int   ol = __shfl_xor_sync(FULLM, bl, off);
                if (ov > bv || (ov == bv && ol < bl)) { bv = ov; bl = ol; }
            }
            last = bv;
            if (lane == bl) v = -FLT_MAX;
        }
        if (lane == 0) s_tau = last;
    }
    __syncthreads();

    float tauR = s_tau;                       // raw-space threshold (shared by both lists)
    float scale = expf(alive_lp[p * D_ + d]);
    bool do0 = (d == 0) && (is_first[p] != 0);
    int fb0 = d * V_ + quar * CHUNK;
    const float4 pad4 = make_float4(PADV, PADV, PADV, PADV);

    // ---- pass 2: filter >= tauR, append candidates ----
    for (int j0 = t; j0 < N4; j0 += 1024) {
        int j1 = j0 + 256, j2 = j0 + 512, j3 = j0 + 768;
        float4 va = base[j0];
        float4 vb = (j1 < N4) ? base[j1] : pad4;
        float4 vc = (j2 < N4) ? base[j2] : pad4;
        float4 vd = (j3 < N4) ? base[j3] : pad4;

        float vmax = fmaxf(fmaxf(max4(va), max4(vb)), fmaxf(max4(vc), max4(vd)));

        if (__ballot_sync(FULLM, vmax >= tauR)) {     // rare
            float4 q[4] = {va, vb, vc, vd};
            int js[4] = {j0, j1, j2, j3};
#pragma unroll
            for (int u = 0; u < 4; u++) {
                if (js[u] >= N4) continue;
                int fb = fb0 + js[u] * 4;
                float vx[4] = {q[u].x, q[u].y, q[u].z, q[u].w};
#pragma unroll
                for (int c = 0; c < 4; c++) {
                    if (vx[c] >= tauR) {
                        int pos = atomicAdd(&g_cnt[p], 1);
                        if (pos < CAP) { g_cv[p * CAP + pos] = vx[c] * scale; g_ci[p * CAP + pos] = fb + c; }
                        if (do0) {                    // d==0: flat idx == token id
                            int pos0 = atomicAdd(&g_cnt0[p], 1);
                            if (pos0 < CAP0) { g_c0v[p * CAP0 + pos0] = vx[c]; g_c0i[p * CAP0 + pos0] = fb + c; }
                        }
                    }
                }
            }
        }
    }
}

// ---------------- block tournament: exact sorted top-16 of (gv,gi)[0..cnt) ---
// 256 threads. Result in bestv/besti (smem[16]), DESC value, ASC idx tie-break.
struct TournScratch {
    float swv[8]; int swi[8]; int swt[8];
    int   s_win;
};

__device__ void block_top16(const float* __restrict__ gv, const int* __restrict__ gi,
                            int cnt, volatile float* bestv, volatile int* besti,
                            TournScratch* sc) {
    int t = threadIdx.x, w = t >> 5, lane = t & 31;
    float rv[17]; int ri[17];
    int ntile = (cnt + TILE - 1) / TILE;
    if (ntile < 1) ntile = 1;

    for (int tile = 0; tile < ntile; tile++) {
        int base = tile * TILE;
#pragma unroll
        for (int k = 0; k < 16; k++) {
            int j = base + k * 256 + t;
            bool ok = (j < cnt);
            rv[k] = ok ? gv[j] : -FLT_MAX;
            ri[k] = ok ? gi[j] : INT_MAX;
        }
        if (tile > 0 && t < 16) { rv[16] = bestv[t]; ri[16] = besti[t]; }
        else                    { rv[16] = -FLT_MAX; ri[16] = INT_MAX; }
        __syncthreads();

        for (int r = 0; r < 16; r++) {
            float bv = rv[0]; int bi = ri[0]; int bs = 0;
#pragma unroll
            for (int k = 1; k < 17; k++)
                if (rv[k] > bv || (rv[k] == bv && ri[k] < bi)) { bv = rv[k]; bi = ri[k]; bs = k; }
            int bt = t;
#pragma unroll
            for (int off = 16; off; off >>= 1) {
                float ov = __shfl_xor_sync(FULLM, bv, off);
                int   oi = __shfl_xor_sync(FULLM, bi, off);
                int   ot = __shfl_xor_sync(FULLM, bt, off);
                if (ov > bv || (ov == bv && oi < bi)) { bv = ov; bi = oi; bt = ot; }
            }
            if (lane == 0) { sc->swv[w] = bv; sc->swi[w] = bi; sc->swt[w] = bt; }
            __syncthreads();
            if (t == 0) {
                float fv = sc->swv[0]; int fi = sc->swi[0]; int ft = sc->swt[0];
#pragma unroll
                for (int q = 1; q < 8; q++)
                    if (sc->swv[q] > fv || (sc->swv[q] == fv && sc->swi[q] < fi)) {
                        fv = sc->swv[q]; fi = sc->swi[q]; ft = sc->swt[q];
                    }
                bestv[r] = fv; besti[r] = fi; sc->s_win = ft;
            }
            __syncthreads();
            if (t == sc->s_win) { rv[bs] = -FLT_MAX; ri[bs] = INT_MAX; }
        }
        __syncthreads();
    }
}

// ---------------- Kernel 2: top-16 + beam-search selection -------------------
__global__ void __launch_bounds__(256)
k2_select(const float* __restrict__ alive_lp, const float* __restrict__ fin_lp,
          const int* __restrict__ still_prompt,
          const int* __restrict__ is_first,
          const int* __restrict__ cur_pos_p, float* __restrict__ out) {
    int p = blockIdx.x;
    int t = threadIdx.x;

    __shared__ float fv[16];  __shared__ int fi[16];
    __shared__ float fv0[16]; __shared__ int fi0[16];
    __shared__ TournScratch sc;

    bool sp = still_prompt[p] != 0;
    bool first = is_first[p] != 0;
    int cnt  = min(g_cnt[p], CAP);
    int cnt0 = min(g_cnt0[p], CAP0);

    if (!sp) {
        block_top16(g_cv + p * CAP, g_ci + p * CAP, cnt, fv, fi, &sc);
        if (first)
            block_top16(g_c0v + p * CAP0, g_c0i + p * CAP0, cnt0, fv0, fi0, &sc);
    }
    __syncthreads();

    if (t == 0) {
        g_cnt[p] = 0; g_cnt0[p] = 0;          // reset for next graph replay
        int cp = *cur_pos_p;

        float lp16[16]; int tok16[16], beam16[16]; bool fin16[16];
        if (!sp) {
            for (int k = 0; k < 16; k++) {
                int idx = fi[k];
                int bm = idx / V_;
                beam16[k] = bm;
                tok16[k]  = idx - bm * V_;
                lp16[k]   = logf(fv[k]);      // log(p*e^a) == a + log p
            }
            if (first) {
                float al0 = alive_lp[p * D_];
                for (int k = 0; k < 16; k++) {
                    tok16[k] = fi0[k];        // flat idx within beam 0 == token
                    lp16[k]  = al0 + logf(fv0[k]);
                }
            }
            for (int k = 0; k < 16; k++) fin16[k] = (tok16[k] == EOS_ID);
        }

        int na[8]; float nav[8];
        int nf[8]; float nfv[8];
        if (!sp) {
            float am[16]; bool used[16];
            for (int k = 0; k < 16; k++) { am[k] = lp16[k] + (fin16[k] ? -MASK_INF : 0.0f); used[k] = false; }
            for (int j = 0; j < 8; j++) {
                int bi = -1; float bv = 0.0f;
                for (int k = 0; k < 16; k++)
                    if (!used[k] && (bi < 0 || am[k] > bv)) { bi = k; bv = am[k]; }
                used[bi] = true; na[j] = bi; nav[j] = bv;
            }
            float cl[24]; bool used2[24];
            for (int j = 0; j < 8; j++) cl[j] = fin_lp[p * D_ + j];
            for (int k = 0; k < 16; k++) cl[8 + k] = lp16[k] + (fin16[k] ? 0.0f : -MASK_INF);
            for (int k = 0; k < 24; k++) used2[k] = false;
            for (int j = 0; j < 8; j++) {
                int bi = -1; float bv = 0.0f;
                for (int k = 0; k < 24; k++)
                    if (!used2[k] && (bi < 0 || cl[k] > bv)) { bi = k; bv = cl[k]; }
                used2[bi] = true; nf[j] = bi; nfv[j] = bv;
            }
        }

        for (int j = 0; j < 8; j++) {
            out[OFF_ATTN + p * D_ + j] = sp ? (float)j : (float)beam16[na[j]];
            out[OFF_ALP  + p * D_ + j] = sp ? alive_lp[p * D_ + j] : nav[j];
            out[OFF_FLP  + p * D_ + j] = sp ? fin_lp[p * D_ + j]   : nfv[j];

            int4 da, df;
            if (sp) {
                da = make_int4(0, j, 0, -1);
                df = make_int4(1, j, 0, -1);
            } else {
                da = make_int4(0, beam16[na[j]], tok16[na[j]], cp);
                if (nf[j] < 8) df = make_int4(1, nf[j], 0, -1);
                else { int k = nf[j] - 8; df = make_int4(0, beam16[k], tok16[k], cp); }
            }
            g_desc[p * D_ + j] = da;
            g_desc[P_ * D_ + p * D_ + j] = df;
        }
    }
}

// ---------------- Kernel 3: gather output sequences --------------------------
__global__ void __launch_bounds__(256)
k3_gather(const int* __restrict__ alive_seq, const int* __restrict__ fin_seq,
          float* __restrict__ out) {
    int r = blockIdx.x;                       // 0..511
    int4 dsc = g_desc[r];
    bool isAlive = r < P_ * D_;
    int rr = isAlive ? r : r - P_ * D_;
    int p = rr >> 3;
    const int* srcbase = (dsc.x ? fin_seq : alive_seq) + (long)(p * D_ + dsc.y) * S_;
    long dst = (isAlive ? (long)OFF_ASEQ : (long)OFF_FSEQ) + (long)rr * S_;
    const int4* s4 = (const int4*)srcbase;
    float4* o4 = (float4*)(out + dst);
    int subpos = dsc.w, tok = dsc.z;
    for (int j = threadIdx.x; j < S_ / 4; j += 256) {
        int4 v = s4[j];
        int base = j * 4;
        if (subpos >= base && subpos < base + 4) {
            int* vp = (int*)&v;
            vp[subpos - base] = tok;
        }
        o4[j] = make_float4((float)v.x, (float)v.y, (float)v.z, (float)v.w);
    }
}

extern "C" void kernel_launch(void* const* d_in, const int* in_sizes, int n_in,
                              void* d_out, int out_size) {
    const float* probs        = (const float*)d_in[0];
    const int*   alive_seq    = (const int*)d_in[1];
    const int*   fin_seq      = (const int*)d_in[2];
    const float* alive_lp     = (const float*)d_in[3];
    const float* fin_lp       = (const float*)d_in[4];
    const int*   still_prompt = (const int*)d_in[5];
    const int*   is_first     = (const int*)d_in[6];
    const int*   cur_pos      = (const int*)d_in[7];
    float* out = (float*)d_out;

    k1_scan<<<P_ * NBLK, 256>>>(probs, alive_lp, still_prompt, is_first);
    k2_select<<<P_, 256>>>(alive_lp, fin_lp, still_prompt, is_first, cur_pos, out);
    k3_gather<<<2 * P_ * D_, 256>>>(alive_seq, fin_seq, out);
}

// round 13
// speedup vs baseline: 1.7257x; 1.6236x over previous
#include <cuda_runtime.h>
#include <cfloat>
#include <climits>
#include <math.h>

// Beam search step: P=32 prompts, D=8 beams, V=128000, S=2048.
// Ordering by alive_lp + log(p) == ordering by m = p * exp(alive_lp) (monotone).
// k1: R10-proven two-pass shape, 64 blocks/prompt for occupancy:
//     pass 1 = full streaming max over the block's 64KB chunk (32 disjoint
//     sub-chunk maxima); tau_b = 16th largest of them (<= block 16th <= global
//     16th, exact-safe). pass 2 = filter-append, 100% L2-resident.
// k2: two concurrent register tournaments (threads 0-127 main list, 128-255
//     beam-0 list; named barriers) + beam-search selection; resets counters.
// k3: 512-block gather/convert of output sequence rows.

#define P_ 32
#define D_ 8
#define V_ 128000
#define S_ 2048
#define NBLK 64          // blocks per prompt in k1 (8 per beam)
#define CHUNK 16000      // elements per k1 block (V/8)
#define NSUB 32          // sub-chunks per block (500 elems each)
#define EOS_ID 2
#define MASK_INF 10000000.0f
#define PADV (-FLT_MAX)
#define CAP  32768       // candidate capacity per prompt (scaled list)
#define CAP0 8192        // candidate capacity per prompt (beam-0 raw list)
#define TILEH 2048       // candidates per half-tournament tile (16 slots * 128 thr)

// output layout (flat float32, tuple concat order)
#define OFF_ATTN 0
#define OFF_ASEQ 256
#define OFF_ALP  524544
#define OFF_FSEQ 524800
#define OFF_FLP  1049088

__device__ int   g_cnt[P_];              // zero-init at load; k2 resets
__device__ int   g_cnt0[P_];
__device__ float g_cv[P_ * CAP];
__device__ int   g_ci[P_ * CAP];
__device__ float g_c0v[P_ * CAP0];
__device__ int   g_c0i[P_ * CAP0];
__device__ int4  g_desc[2 * P_ * D_];    // {buf(0=alive,1=fin), src_beam, token, subpos(-1 none)}

#define FULLM 0xffffffffu
#define HBAR(id) asm volatile("bar.sync %0, %1;" :: "r"(id), "r"(128) : "memory")

__device__ __forceinline__ float max4(float4 v) {
    return fmaxf(fmaxf(v.x, v.y), fmaxf(v.z, v.w));
}

// ---------------- Kernel 1: self-thresholding scan + candidate append --------
__global__ void __launch_bounds__(256)
k1_scan(const float* __restrict__ probs, const float* __restrict__ alive_lp,
        const int* __restrict__ still_prompt, const int* __restrict__ is_first) {
    int blk = blockIdx.x;
    int p = blk >> 6;
    if (still_prompt[p]) return;              // passthrough prompt: no work
    int b = blk & 63;
    int d = b >> 3;
    int part = b & 7;
    int t = threadIdx.x, w = t >> 5, lane = t & 31;

    __shared__ float scm[NSUB];
    __shared__ float s_tau;

    const float4* base = (const float4*)(probs + (long)(p * D_ + d) * V_ + part * CHUNK);
    const int N4 = CHUNK / 4;                 // 4000 float4s
    const int SUB4 = N4 / NSUB;               // 125 float4s per sub-chunk

    // ---- pass 1: 32 sub-chunk maxima; 4 independent load streams per lane ----
    {
        const float4* sb0 = base + (w +  0) * SUB4;
        const float4* sb1 = base + (w +  8) * SUB4;
        const float4* sb2 = base + (w + 16) * SUB4;
        const float4* sb3 = base + (w + 24) * SUB4;
        float m0 = -FLT_MAX, m1 = -FLT_MAX, m2 = -FLT_MAX, m3 = -FLT_MAX;
        for (int i = lane; i < SUB4; i += 32) {
            m0 = fmaxf(m0, max4(sb0[i]));
            m1 = fmaxf(m1, max4(sb1[i]));
            m2 = fmaxf(m2, max4(sb2[i]));
            m3 = fmaxf(m3, max4(sb3[i]));
        }
#pragma unroll
        for (int off = 16; off; off >>= 1) {
            m0 = fmaxf(m0, __shfl_xor_sync(FULLM, m0, off));
            m1 = fmaxf(m1, __shfl_xor_sync(FULLM, m1, off));
            m2 = fmaxf(m2, __shfl_xor_sync(FULLM, m2, off));
            m3 = fmaxf(m3, __shfl_xor_sync(FULLM, m3, off));
        }
        if (lane == 0) { scm[w] = m0; scm[w + 8] = m1; scm[w + 16] = m2; scm[w + 24] = m3; }
    }
    __syncthreads();

    // ---- tau_b = 16th largest of the 32 maxima (warp 0, argmax-invalidate) ----
    if (w == 0) {
        float v = scm[lane];
        float last = -FLT_MAX;
#pragma unroll
        for (int k = 0; k < 16; k++) {
            float bv = v; int bl = lane;
#pragma unroll
            for (int off = 16; off; off >>= 1) {
                float ov = __shfl_xor_sync(FULLM, bv, off);
                int   ol = __shfl_xor_sync(FULLM, bl, off);
                if (ov > bv || (ov == bv && ol < bl)) { bv = ov; bl = ol; }
            }
            last = bv;
            if (lane == bl) v = -FLT_MAX;
        }
        if (lane == 0) s_tau = last;
    }
    __syncthreads();

    float tauR = s_tau;                       // raw-space threshold (shared by both lists)
    float scale = expf(alive_lp[p * D_ + d]);
    bool do0 = (d == 0) && (is_first[p] != 0);
    int fb0 = d * V_ + part * CHUNK;
    const float4 pad4 = make_float4(PADV, PADV, PADV, PADV);

    // ---- pass 2: filter >= tauR (L2-resident re-read), append candidates ----
    for (int j0 = t; j0 < N4; j0 += 1024) {
        int j1 = j0 + 256, j2 = j0 + 512, j3 = j0 + 768;
        float4 va = base[j0];
        float4 vb = (j1 < N4) ? base[j1] : pad4;
        float4 vc = (j2 < N4) ? base[j2] : pad4;
        float4 vd = (j3 < N4) ? base[j3] : pad4;

        float vmax = fmaxf(fmaxf(max4(va), max4(vb)), fmaxf(max4(vc), max4(vd)));

        if (__ballot_sync(FULLM, vmax >= tauR)) {     // rare
            float4 q[4] = {va, vb, vc, vd};
            int js[4] = {j0, j1, j2, j3};
#pragma unroll
            for (int u = 0; u < 4; u++) {
                if (js[u] >= N4) continue;
                int fb = fb0 + js[u] * 4;
                float vx[4] = {q[u].x, q[u].y, q[u].z, q[u].w};
#pragma unroll
                for (int c = 0; c < 4; c++) {
                    if (vx[c] >= tauR) {
                        int pos = atomicAdd(&g_cnt[p], 1);
                        if (pos < CAP) { g_cv[p * CAP + pos] = vx[c] * scale; g_ci[p * CAP + pos] = fb + c; }
                        if (do0) {                    // d==0: flat idx == token id
                            int pos0 = atomicAdd(&g_cnt0[p], 1);
                            if (pos0 < CAP0) { g_c0v[p * CAP0 + pos0] = vx[c]; g_c0i[p * CAP0 + pos0] = fb + c; }
                        }
                    }
                }
            }
        }
    }
}

// -------- half-block tournament: sorted top-16, 128 threads, named barrier ---
struct HalfScratch {
    float swv[4]; int swi[4]; int swt[4];
    int   s_win;
};

__device__ void half_top16(const float* __restrict__ gv, const int* __restrict__ gi,
                           int cnt, volatile float* bestv, volatile int* besti,
                           volatile HalfScratch* sc, int tb, int barid) {
    int t = threadIdx.x;
    int lt = t - tb;                          // 0..127
    int w2 = lt >> 5;                         // 0..3
    int lane = t & 31;
    float rv[17]; int ri[17];
    int ntile = (cnt + TILEH - 1) / TILEH;
    if (ntile < 1) ntile = 1;

    for (int tile = 0; tile < ntile; tile++) {
        int base = tile * TILEH;
#pragma unroll
        for (int k = 0; k < 16; k++) {
            int j = base + k * 128 + lt;
            bool ok = (j < cnt);
            rv[k] = ok ? gv[j] : -FLT_MAX;
            ri[k] = ok ? gi[j] : INT_MAX;
        }
        if (tile > 0 && lt < 16) { rv[16] = bestv[lt]; ri[16] = besti[lt]; }
        else                     { rv[16] = -FLT_MAX; ri[16] = INT_MAX; }

        for (int r = 0; r < 16; r++) {
            float bv = rv[0]; int bi = ri[0]; int bs = 0;
#pragma unroll
            for (int k = 1; k < 17; k++)
                if (rv[k] > bv || (rv[k] == bv && ri[k] < bi)) { bv = rv[k]; bi = ri[k]; bs = k; }
            int bt = lt;
#pragma unroll
            for (int off = 16; off; off >>= 1) {
                float ov = __shfl_xor_sync(FULLM, bv, off);
                int   oi = __shfl_xor_sync(FULLM, bi, off);
                int   ot = __shfl_xor_sync(FULLM, bt, off);
                if (ov > bv || (ov == bv && oi < bi)) { bv = ov; bi = oi; bt = ot; }
            }
            if (lane == 0) { sc->swv[w2] = bv; sc->swi[w2] = bi; sc->swt[w2] = bt; }
            HBAR(barid);
            if (lt == 0) {
                float fv = sc->swv[0]; int fi = sc->swi[0]; int ft = sc->swt[0];
#pragma unroll
                for (int q = 1; q < 4; q++)
                    if (sc->swv[q] > fv || (sc->swv[q] == fv && sc->swi[q] < fi)) {
                        fv = sc->swv[q]; fi = sc->swi[q]; ft = sc->swt[q];
                    }
                bestv[r] = fv; besti[r] = fi; sc->s_win = ft;
            }
            HBAR(barid);
            if (lt == sc->s_win) { rv[bs] = -FLT_MAX; ri[bs] = INT_MAX; }
        }
        HBAR(barid);
    }
}

// ---------------- Kernel 2: dual tournament + beam-search selection ----------
__global__ void __launch_bounds__(256)
k2_select(const float* __restrict__ alive_lp, const float* __restrict__ fin_lp,
          const int* __restrict__ still_prompt,
          const int* __restrict__ is_first,
          const int* __restrict__ cur_pos_p, float* __restrict__ out) {
    int p = blockIdx.x;
    int t = threadIdx.x;

    __shared__ float fv[16];  __shared__ int fi[16];
    __shared__ float fv0[16]; __shared__ int fi0[16];
    __shared__ HalfScratch scA, scB;

    bool sp = still_prompt[p] != 0;
    bool first = is_first[p] != 0;
    int cnt  = min(g_cnt[p], CAP);
    int cnt0 = min(g_cnt0[p], CAP0);

    if (!sp) {
        if (t < 128)
            half_top16(g_cv + p * CAP, g_ci + p * CAP, cnt, fv, fi,
                       (volatile HalfScratch*)&scA, 0, 1);
        else if (first)
            half_top16(g_c0v + p * CAP0, g_c0i + p * CAP0, cnt0, fv0, fi0,
                       (volatile HalfScratch*)&scB, 128, 2);
    }
    __syncthreads();

    if (t == 0) {
        g_cnt[p] = 0; g_cnt0[p] = 0;          // reset for next graph replay
        int cp = *cur_pos_p;

        float lp16[16]; int tok16[16], beam16[16]; bool fin16[16];
        if (!sp) {
            for (int k = 0; k < 16; k++) {
                int idx = fi[k];
                int bm = idx / V_;
                beam16[k] = bm;
                tok16[k]  = idx - bm * V_;
                lp16[k]   = logf(fv[k]);      // log(p*e^a) == a + log p
            }
            if (first) {
                float al0 = alive_lp[p * D_];
                for (int k = 0; k < 16; k++) {
                    tok16[k] = fi0[k];        // flat idx within beam 0 == token
                    lp16[k]  = al0 + logf(fv0[k]);
                }
            }
            for (int k = 0; k < 16; k++) fin16[k] = (tok16[k] == EOS_ID);
        }

        int na[8]; float nav[8];
        int nf[8]; float nfv[8];
        if (!sp) {
            float am[16]; bool used[16];
            for (int k = 0; k < 16; k++) { am[k] = lp16[k] + (fin16[k] ? -MASK_INF : 0.0f); used[k] = false; }
            for (int j = 0; j < 8; j++) {
                int bi = -1; float bv = 0.0f;
                for (int k = 0; k < 16; k++)
                    if (!used[k] && (bi < 0 || am[k] > bv)) { bi = k; bv = am[k]; }
                used[bi] = true; na[j] = bi; nav[j] = bv;
            }
            float cl[24]; bool used2[24];
            for (int j = 0; j < 8; j++) cl[j] = fin_lp[p * D_ + j];
            for (int k = 0; k < 16; k++) cl[8 + k] = lp16[k] + (fin16[k] ? 0.0f : -MASK_INF);
            for (int k = 0; k < 24; k++) used2[k] = false;
            for (int j = 0; j < 8; j++) {
                int bi = -1; float bv = 0.0f;
                for (int k = 0; k < 24; k++)
                    if (!used2[k] && (bi < 0 || cl[k] > bv)) { bi = k; bv = cl[k]; }
                used2[bi] = true; nf[j] = bi; nfv[j] = bv;
            }
        }

        for (int j = 0; j < 8; j++) {
            out[OFF_ATTN + p * D_ + j] = sp ? (float)j : (float)beam16[na[j]];
            out[OFF_ALP  + p * D_ + j] = sp ? alive_lp[p * D_ + j] : nav[j];
            out[OFF_FLP  + p * D_ + j] = sp ? fin_lp[p * D_ + j]   : nfv[j];

            int4 da, df;
            if (sp) {
                da = make_int4(0, j, 0, -1);
                df = make_int4(1, j, 0, -1);
            } else {
                da = make_int4(0, beam16[na[j]], tok16[na[j]], cp);
                if (nf[j] < 8) df = make_int4(1, nf[j], 0, -1);
                else { int k = nf[j] - 8; df = make_int4(0, beam16[k], tok16[k], cp); }
            }
            g_desc[p * D_ + j] = da;
            g_desc[P_ * D_ + p * D_ + j] = df;
        }
    }
}

// ---------------- Kernel 3: gather output sequences --------------------------
__global__ void __launch_bounds__(256)
k3_gather(const int* __restrict__ alive_seq, const int* __restrict__ fin_seq,
          float* __restrict__ out) {
    int r = blockIdx.x;                       // 0..511
    int4 dsc = g_desc[r];
    bool isAlive = r < P_ * D_;
    int rr = isAlive ? r : r - P_ * D_;
    int p = rr >> 3;
    const int* srcbase = (dsc.x ? fin_seq : alive_seq) + (long)(p * D_ + dsc.y) * S_;
    long dst = (isAlive ? (long)OFF_ASEQ : (long)OFF_FSEQ) + (long)rr * S_;
    const int4* s4 = (const int4*)srcbase;
    float4* o4 = (float4*)(out + dst);
    int subpos = dsc.w, tok = dsc.z;
    for (int j = threadIdx.x; j < S_ / 4; j += 256) {
        int4 v = s4[j];
        int base = j * 4;
        if (subpos >= base && subpos < base + 4) {
            int* vp = (int*)&v;
            vp[subpos - base] = tok;
        }
        o4[j] = make_float4((float)v.x, (float)v.y, (float)v.z, (float)v.w);
    }
}

extern "C" void kernel_launch(void* const* d_in, const int* in_sizes, int n_in,
                              void* d_out, int out_size) {
    const float* probs        = (const float*)d_in[0];
    const int*   alive_seq    = (const int*)d_in[1];
    const int*   fin_seq      = (const int*)d_in[2];
    const float* alive_lp     = (const float*)d_in[3];
    const float* fin_lp       = (const float*)d_in[4];
    const int*   still_prompt = (const int*)d_in[5];
    const int*   is_first     = (const int*)d_in[6];
    const int*   cur_pos      = (const int*)d_in[7];
    float* out = (float*)d_out;

    k1_scan<<<P_ * NBLK, 256>>>(probs, alive_lp, still_prompt, is_first);
    k2_select<<<P_, 256>>>(alive_lp, fin_lp, still_prompt, is_first, cur_pos, out);
    k3_gather<<<2 * P_ * D_, 256>>>(alive_seq, fin_seq, out);
}

// round 14
// speedup vs baseline: 1.7545x; 1.0167x over previous
#include <cuda_runtime.h>
#include <cfloat>
#include <climits>
#include <math.h>

// Beam search step: P=32 prompts, D=8 beams, V=128000, S=2048.
// Ordering by alive_lp + log(p) == ordering by m = p * exp(alive_lp) (monotone).
// k1: pass 1 = 125 chunk maxima (1 warp-load chunk = 128 elems) streaming the
//     block's 64KB once from DRAM; tau_b = 16th largest of the 125 maxima
//     (<= block 16th <= global 16th, exact-safe). pass 2 re-reads ONLY the
//     ~17/125 chunks whose max >= tau_b (warp-uniform skip, L2-hit) and
//     appends survivors. still_prompt prompts skipped entirely.
// k2: dual concurrent register tournaments (named barriers) + selection.
// k3: 512-block gather/convert of output sequence rows.

#define P_ 32
#define D_ 8
#define V_ 128000
#define S_ 2048
#define NBLK 64          // blocks per prompt in k1 (8 per beam)
#define CHUNK 16000      // elements per k1 block (V/8) = 4000 float4
#define NC 125           // chunks per block (32 float4 = 128 elems each)
#define EOS_ID 2
#define MASK_INF 10000000.0f
#define CAP  32768       // candidate capacity per prompt (scaled list)
#define CAP0 8192        // candidate capacity per prompt (beam-0 raw list)
#define TILEH 2048       // candidates per half-tournament tile (16 slots * 128 thr)

// output layout (flat float32, tuple concat order)
#define OFF_ATTN 0
#define OFF_ASEQ 256
#define OFF_ALP  524544
#define OFF_FSEQ 524800
#define OFF_FLP  1049088

__device__ int   g_cnt[P_];              // zero-init at load; k2 resets
__device__ int   g_cnt0[P_];
__device__ float g_cv[P_ * CAP];
__device__ int   g_ci[P_ * CAP];
__device__ float g_c0v[P_ * CAP0];
__device__ int   g_c0i[P_ * CAP0];
__device__ int4  g_desc[2 * P_ * D_];    // {buf(0=alive,1=fin), src_beam, token, subpos(-1 none)}

#define FULLM 0xffffffffu
#define HBAR(id) asm volatile("bar.sync %0, %1;" :: "r"(id), "r"(128) : "memory")

__device__ __forceinline__ float max4(float4 v) {
    return fmaxf(fmaxf(v.x, v.y), fmaxf(v.z, v.w));
}

// ---------------- Kernel 1: fine-chunk self-threshold + sparse re-read ------
__global__ void __launch_bounds__(256)
k1_scan(const float* __restrict__ probs, const float* __restrict__ alive_lp,
        const int* __restrict__ still_prompt, const int* __restrict__ is_first) {
    int blk = blockIdx.x;
    int p = blk >> 6;
    if (still_prompt[p]) return;              // passthrough prompt: no work
    int b = blk & 63;
    int d = b >> 3;
    int part = b & 7;
    int t = threadIdx.x, w = t >> 5, lane = t & 31;

    __shared__ float scm[NC];
    __shared__ float s_tau;

    const float4* base = (const float4*)(probs + (long)(p * D_ + d) * V_ + part * CHUNK);

    // ---- pass 1: 125 chunk maxima, one coalesced warp-load per chunk --------
    for (int c = w; c < NC; c += 8) {
        float m = max4(base[c * 32 + lane]);
#pragma unroll
        for (int off = 16; off; off >>= 1)
            m = fmaxf(m, __shfl_xor_sync(FULLM, m, off));
        if (lane == 0) scm[c] = m;
    }
    __syncthreads();

    // ---- tau_b = 16th largest of the 125 maxima (warp 0) -------------------
    if (w == 0) {
        float vv[4];
        vv[0] = scm[lane];
        vv[1] = (lane + 32 < NC) ? scm[lane + 32] : -FLT_MAX;
        vv[2] = (lane + 64 < NC) ? scm[lane + 64] : -FLT_MAX;
        vv[3] = (lane + 96 < NC) ? scm[lane + 96] : -FLT_MAX;
        float last = -FLT_MAX;
#pragma unroll
        for (int k = 0; k < 16; k++) {
            float bv = vv[0]; int bs = 0;
#pragma unroll
            for (int j = 1; j < 4; j++)
                if (vv[j] > bv) { bv = vv[j]; bs = j; }
            float cb = bv; int cl = lane;
#pragma unroll
            for (int off = 16; off; off >>= 1) {
                float ov = __shfl_xor_sync(FULLM, cb, off);
                int   ol = __shfl_xor_sync(FULLM, cl, off);
                if (ov > cb || (ov == cb && ol < cl)) { cb = ov; cl = ol; }
            }
            last = cb;
            if (lane == cl) vv[bs] = -FLT_MAX;
        }
        if (lane == 0) s_tau = last;
    }
    __syncthreads();

    float tauR = s_tau;                       // raw-space threshold (shared by both lists)
    float scale = expf(alive_lp[p * D_ + d]);
    bool do0 = (d == 0) && (is_first[p] != 0);
    int fb0 = d * V_ + part * CHUNK;

    // ---- pass 2: re-read ONLY chunks with max >= tau (warp-uniform skip) ----
    for (int c = w; c < NC; c += 8) {
        if (scm[c] < tauR) continue;          // ~86% skipped
        float4 v = base[c * 32 + lane];       // L2-hit
        int fb = fb0 + (c * 32 + lane) * 4;
        float vx[4] = {v.x, v.y, v.z, v.w};
#pragma unroll
        for (int cc = 0; cc < 4; cc++) {
            if (vx[cc] >= tauR) {
                int pos = atomicAdd(&g_cnt[p], 1);
                if (pos < CAP) { g_cv[p * CAP + pos] = vx[cc] * scale; g_ci[p * CAP + pos] = fb + cc; }
                if (do0) {                    // d==0: flat idx == token id
                    int pos0 = atomicAdd(&g_cnt0[p], 1);
                    if (pos0 < CAP0) { g_c0v[p * CAP0 + pos0] = vx[cc]; g_c0i[p * CAP0 + pos0] = fb + cc; }
                }
            }
        }
    }
}

// -------- half-block tournament: sorted top-16, 128 threads, named barrier ---
struct HalfScratch {
    float swv[4]; int swi[4]; int swt[4];
    int   s_win;
};

__device__ void half_top16(const float* __restrict__ gv, const int* __restrict__ gi,
                           int cnt, volatile float* bestv, volatile int* besti,
                           volatile HalfScratch* sc, int tb, int barid) {
    int t = threadIdx.x;
    int lt = t - tb;                          // 0..127
    int w2 = lt >> 5;                         // 0..3
    int lane = t & 31;
    float rv[17]; int ri[17];
    int ntile = (cnt + TILEH - 1) / TILEH;
    if (ntile < 1) ntile = 1;

    for (int tile = 0; tile < ntile; tile++) {
        int base = tile * TILEH;
#pragma unroll
        for (int k = 0; k < 16; k++) {
            int j = base + k * 128 + lt;
            bool ok = (j < cnt);
            rv[k] = ok ? gv[j] : -FLT_MAX;
            ri[k] = ok ? gi[j] : INT_MAX;
        }
        if (tile > 0 && lt < 16) { rv[16] = bestv[lt]; ri[16] = besti[lt]; }
        else                     { rv[16] = -FLT_MAX; ri[16] = INT_MAX; }

        for (int r = 0; r < 16; r++) {
            float bv = rv[0]; int bi = ri[0]; int bs = 0;
#pragma unroll
            for (int k = 1; k < 17; k++)
                if (rv[k] > bv || (rv[k] == bv && ri[k] < bi)) { bv = rv[k]; bi = ri[k]; bs = k; }
            int bt = lt;
#pragma unroll
            for (int off = 16; off; off >>= 1) {
                float ov = __shfl_xor_sync(FULLM, bv, off);
                int   oi = __shfl_xor_sync(FULLM, bi, off);
                int   ot = __shfl_xor_sync(FULLM, bt, off);
                if (ov > bv || (ov == bv && oi < bi)) { bv = ov; bi = oi; bt = ot; }
            }
            if (lane == 0) { sc->swv[w2] = bv; sc->swi[w2] = bi; sc->swt[w2] = bt; }
            HBAR(barid);
            if (lt == 0) {
                float fv = sc->swv[0]; int fi = sc->swi[0]; int ft = sc->swt[0];
#pragma unroll
                for (int q = 1; q < 4; q++)
                    if (sc->swv[q] > fv || (sc->swv[q] == fv && sc->swi[q] < fi)) {
                        fv = sc->swv[q]; fi = sc->swi[q]; ft = sc->swt[q];
                    }
                bestv[r] = fv; besti[r] = fi; sc->s_win = ft;
            }
            HBAR(barid);
            if (lt == sc->s_win) { rv[bs] = -FLT_MAX; ri[bs] = INT_MAX; }
        }
        HBAR(barid);
    }
}

// ---------------- Kernel 2: dual tournament + beam-search selection ----------
__global__ void __launch_bounds__(256)
k2_select(const float* __restrict__ alive_lp, const float* __restrict__ fin_lp,
          const int* __restrict__ still_prompt,
          const int* __restrict__ is_first,
          const int* __restrict__ cur_pos_p, float* __restrict__ out) {
    int p = blockIdx.x;
    int t = threadIdx.x;

    __shared__ float fv[16];  __shared__ int fi[16];
    __shared__ float fv0[16]; __shared__ int fi0[16];
    __shared__ HalfScratch scA, scB;

    bool sp = still_prompt[p] != 0;
    bool first = is_first[p] != 0;
    int cnt  = min(g_cnt[p], CAP);
    int cnt0 = min(g_cnt0[p], CAP0);

    if (!sp) {
        if (t < 128)
            half_top16(g_cv + p * CAP, g_ci + p * CAP, cnt, fv, fi,
                       (volatile HalfScratch*)&scA, 0, 1);
        else if (first)
            half_top16(g_c0v + p * CAP0, g_c0i + p * CAP0, cnt0, fv0, fi0,
                       (volatile HalfScratch*)&scB, 128, 2);
    }
    __syncthreads();

    if (t == 0) {
        g_cnt[p] = 0; g_cnt0[p] = 0;          // reset for next graph replay
        int cp = *cur_pos_p;

        float lp16[16]; int tok16[16], beam16[16]; bool fin16[16];
        if (!sp) {
            for (int k = 0; k < 16; k++) {
                int idx = fi[k];
                int bm = idx / V_;
                beam16[k] = bm;
                tok16[k]  = idx - bm * V_;
                lp16[k]   = logf(fv[k]);      // log(p*e^a) == a + log p
            }
            if (first) {
                float al0 = alive_lp[p * D_];
                for (int k = 0; k < 16; k++) {
                    tok16[k] = fi0[k];        // flat idx within beam 0 == token
                    lp16[k]  = al0 + logf(fv0[k]);
                }
            }
            for (int k = 0; k < 16; k++) fin16[k] = (tok16[k] == EOS_ID);
        }

        int na[8]; float nav[8];
        int nf[8]; float nfv[8];
        if (!sp) {
            float am[16]; bool used[16];
            for (int k = 0; k < 16; k++) { am[k] = lp16[k] + (fin16[k] ? -MASK_INF : 0.0f); used[k] = false; }
            for (int j = 0; j < 8; j++) {
                int bi = -1; float bv = 0.0f;
                for (int k = 0; k < 16; k++)
                    if (!used[k] && (bi < 0 || am[k] > bv)) { bi = k; bv = am[k]; }
                used[bi] = true; na[j] = bi; nav[j] = bv;
            }
            float cl[24]; bool used2[24];
            for (int j = 0; j < 8; j++) cl[j] = fin_lp[p * D_ + j];
            for (int k = 0; k < 16; k++) cl[8 + k] = lp16[k] + (fin16[k] ? 0.0f : -MASK_INF);
            for (int k = 0; k < 24; k++) used2[k] = false;
            for (int j = 0; j < 8; j++) {
                int bi = -1; float bv = 0.0f;
                for (int k = 0; k < 24; k++)
                    if (!used2[k] && (bi < 0 || cl[k] > bv)) { bi = k; bv = cl[k]; }
                used2[bi] = true; nf[j] = bi; nfv[j] = bv;
            }
        }

        for (int j = 0; j < 8; j++) {
            out[OFF_ATTN + p * D_ + j] = sp ? (float)j : (float)beam16[na[j]];
            out[OFF_ALP  + p * D_ + j] = sp ? alive_lp[p * D_ + j] : nav[j];
            out[OFF_FLP  + p * D_ + j] = sp ? fin_lp[p * D_ + j]   : nfv[j];

            int4 da, df;
            if (sp) {
                da = make_int4(0, j, 0, -1);
                df = make_int4(1, j, 0, -1);
            } else {
                da = make_int4(0, beam16[na[j]], tok16[na[j]], cp);
                if (nf[j] < 8) df = make_int4(1, nf[j], 0, -1);
                else { int k = nf[j] - 8; df = make_int4(0, beam16[k], tok16[k], cp); }
            }
            g_desc[p * D_ + j] = da;
            g_desc[P_ * D_ + p * D_ + j] = df;
        }
    }
}

// ---------------- Kernel 3: gather output sequences --------------------------
__global__ void __launch_bounds__(256)
k3_gather(const int* __restrict__ alive_seq, const int* __restrict__ fin_seq,
          float* __restrict__ out) {
    int r = blockIdx.x;                       // 0..511
    int4 dsc = g_desc[r];
    bool isAlive = r < P_ * D_;
    int rr = isAlive ? r : r - P_ * D_;
    int p = rr >> 3;
    const int* srcbase = (dsc.x ? fin_seq : alive_seq) + (long)(p * D_ + dsc.y) * S_;
    long dst = (isAlive ? (long)OFF_ASEQ : (long)OFF_FSEQ) + (long)rr * S_;
    const int4* s4 = (const int4*)srcbase;
    float4* o4 = (float4*)(out + dst);
    int subpos = dsc.w, tok = dsc.z;
    for (int j = threadIdx.x; j < S_ / 4; j += 256) {
        int4 v = s4[j];
        int base = j * 4;
        if (subpos >= base && subpos < base + 4) {
            int* vp = (int*)&v;
            vp[subpos - base] = tok;
        }
        o4[j] = make_float4((float)v.x, (float)v.y, (float)v.z, (float)v.w);
    }
}

extern "C" void kernel_launch(void* const* d_in, const int* in_sizes, int n_in,
                              void* d_out, int out_size) {
    const float* probs        = (const float*)d_in[0];
    const int*   alive_seq    = (const int*)d_in[1];
    const int*   fin_seq      = (const int*)d_in[2];
    const float* alive_lp     = (const float*)d_in[3];
    const float* fin_lp       = (const float*)d_in[4];
    const int*   still_prompt = (const int*)d_in[5];
    const int*   is_first     = (const int*)d_in[6];
    const int*   cur_pos      = (const int*)d_in[7];
    float* out = (float*)d_out;

    k1_scan<<<P_ * NBLK, 256>>>(probs, alive_lp, still_prompt, is_first);
    k2_select<<<P_, 256>>>(alive_lp, fin_lp, still_prompt, is_first, cur_pos, out);
    k3_gather<<<2 * P_ * D_, 256>>>(alive_seq, fin_seq, out);
}